// round 16
// baseline (speedup 1.0000x reference)
#include <cuda_runtime.h>
#include <cstdint>

#define N_Q 4096
#define NTHREADS 1024
#define NCTAS 18
#define EVAL_PT_SCORE 0.05f
#define D2_THRESH 25.0f   // 5.0^2
#define NBR_CAP 6
#define OVF 255
#define BINCAP 1024
#define NBUCK 1024
#define PREP_ITEMS 8192
#define ITEMS_PER_CTA ((PREP_ITEMS + NCTAS - 1) / NCTAS)   // 456

// resolver smem: brec uint4[1024] | scs int[1025] | ccu int[1024] | hidx u16[1024]
//  | wl u16[1024] | rlist u16[1024] | nbr u16[6144] | lstat u8[1024] | nbrcnt u8[1024]
//  | warpsum int[32]  => 45,188
// builder smem:  bkey u64[4096] | cs int[1025] | ccu int[1024] | warpsum int[32] => 41,092
#define SMEM_BYTES 45192

// -------- device scratch --------
__device__ uint4 g_binrec[2][8][BINCAP];        // (keylo,keyhi,x,y) per stripe bin
__device__ unsigned short g_binidx[2][8][BINCAP];
__device__ int g_bincnt[2][8];
__device__ unsigned long long g_key[2][N_Q];
__device__ int g_stat[2][N_Q];                  // 0 pending / 1 retained / 2 suppressed
__device__ unsigned short g_rank[2][N_Q];
__device__ int g_rankdone[2];
__device__ int g_arrive;
__device__ int g_depart;

__device__ __forceinline__ int warp_incl_scan(int v) {
    int lane = threadIdx.x & 31;
    #pragma unroll
    for (int o = 1; o < 32; o <<= 1) {
        int n = __shfl_up_sync(0xffffffffu, v, o);
        if (lane >= o) v += n;
    }
    return v;
}

__device__ __forceinline__ unsigned long long mk_key(float s, int i) {
    bool valid = (s >= EVAL_PT_SCORE);
    unsigned int fb = __float_as_uint(s);
    return valid
        ? ((((unsigned long long)fb) << 32) | (unsigned int)(N_Q - 1 - i))
        : (unsigned long long)(unsigned int)(N_Q - 1 - i);
}

__global__ void __launch_bounds__(NTHREADS, 1)
nms_fused_kernel(const float* __restrict__ logits,
                 const float* __restrict__ boxes,
                 const float* __restrict__ ts,
                 float* __restrict__ out) {
    const int tid = threadIdx.x;
    const int lane = tid & 31;
    const int wid = tid >> 5;
    extern __shared__ unsigned char sm[];

    // ================= phase 0: distributed prep =================
    {
        const int base = blockIdx.x * ITEMS_PER_CTA;
        const int end = min(base + ITEMS_PER_CTA, PREP_ITEMS);
        for (int t = base + tid; t < end; t += NTHREADS) {
            int cls = t >> 12;
            int j = t & (N_Q - 1);
            float l0 = logits[3 * j + 0];
            float l1 = logits[3 * j + 1];
            float l2 = logits[3 * j + 2];
            float m = fmaxf(l0, fmaxf(l1, l2));
            float e0 = __expf(l0 - m), e1 = __expf(l1 - m), e2 = __expf(l2 - m);
            float inv = __fdividef(1.0f, e0 + e1 + e2);
            float p0 = e0 * inv, p1 = e1 * inv, p2 = e2 * inv;
            float x = boxes[2 * j + 0] * ts[0];
            float y = boxes[2 * j + 1] * ts[1];
            float s = cls ? p1 : p0;
            unsigned long long key = mk_key(s, j);
            g_key[cls][j] = key;
            g_stat[cls][j] = (s >= EVAL_PT_SCORE) ? 0 : 2;

            int cy = min(63, max(0, (int)(y * 0.125f)));
            uint4 rec = make_uint4((unsigned int)key, (unsigned int)(key >> 32),
                                   __float_as_uint(x), __float_as_uint(y));
            int b0 = cy >> 3, mrow = cy & 7;
            {
                int pos = atomicAdd(&g_bincnt[cls][b0], 1);
                if (pos < BINCAP) {
                    g_binrec[cls][b0][pos] = rec;
                    g_binidx[cls][b0][pos] = (unsigned short)j;
                }
            }
            if (mrow == 0 && b0 > 0) {
                int pos = atomicAdd(&g_bincnt[cls][b0 - 1], 1);
                if (pos < BINCAP) {
                    g_binrec[cls][b0 - 1][pos] = rec;
                    g_binidx[cls][b0 - 1][pos] = (unsigned short)j;
                }
            }
            if (mrow == 7 && b0 < 7) {
                int pos = atomicAdd(&g_bincnt[cls][b0 + 1], 1);
                if (pos < BINCAP) {
                    g_binrec[cls][b0 + 1][pos] = rec;
                    g_binidx[cls][b0 + 1][pos] = (unsigned short)j;
                }
            }
            if (cls == 0) {
                out[5 * j + 0] = 1.0f - p2;
                out[5 * j + 1] = x;
                out[5 * j + 2] = y;
                out[5 * j + 3] = 0.0f;
            } else {
                out[5 * j + 4] = 0.0f;
            }
        }
    }
    // grid-wide sense barrier through L2
    __threadfence();
    __syncthreads();
    if (tid == 0) {
        atomicAdd(&g_arrive, 1);
        volatile int* va = &g_arrive;
        while (*va < NCTAS) { }
    }
    __syncthreads();
    __threadfence();

    // ================= phase 1 =================
    if (blockIdx.x >= 16) {
        // ======== rank builder for class cls ========
        const int cls = blockIdx.x - 16;
        unsigned long long* bkey = (unsigned long long*)sm;        // [N_Q]
        int* cs  = (int*)(bkey + N_Q);                             // [NBUCK+1]
        int* ccu = cs + (NBUCK + 1);                               // [NBUCK]
        int* warpsum = ccu + NBUCK;                                // [32]

        cs[tid] = 0;
        if (tid == 0) cs[NBUCK] = 0;
        __syncthreads();

        unsigned long long k4[4];
        int b4[4];
        #pragma unroll
        for (int k = 0; k < 4; k++) {
            int j = k * NTHREADS + tid;
            unsigned long long key = g_key[cls][j];
            k4[k] = key;
            if (key >> 32) {
                float s = __uint_as_float((unsigned int)(key >> 32));
                b4[k] = min(NBUCK - 1, (int)(s * (float)NBUCK));
                atomicAdd(&cs[b4[k]], 1);
            } else b4[k] = 0;
        }
        __syncthreads();
        {
            int v = cs[tid];
            int iv = warp_incl_scan(v);
            if (lane == 31) warpsum[wid] = iv;
            __syncthreads();
            if (wid == 0) warpsum[lane] = warp_incl_scan(warpsum[lane]);
            __syncthreads();
            int ex = iv - v + (wid ? warpsum[wid - 1] : 0);
            cs[tid] = ex; ccu[tid] = ex;
            if (tid == NTHREADS - 1) cs[NBUCK] = ex + v;
        }
        __syncthreads();
        const int nv = cs[NBUCK];
        #pragma unroll
        for (int k = 0; k < 4; k++) {
            if (k4[k] >> 32) {
                int bp = atomicAdd(&ccu[b4[k]], 1);
                bkey[bp] = k4[k];
            }
        }
        __syncthreads();
        #pragma unroll
        for (int k = 0; k < 4; k++) {
            if (!(k4[k] >> 32)) continue;
            int b = b4[k];
            int r = nv - cs[b + 1];
            int e = cs[b + 1];
            for (int q = cs[b]; q < e; q++)
                if (bkey[q] > k4[k]) r++;
            g_rank[cls][k * NTHREADS + tid] = (unsigned short)r;
        }
        __syncthreads();
        __threadfence();
        if (tid == 0) g_rankdone[cls] = 1;
    } else {
        // ======== stripe resolver ========
        const int rank = blockIdx.x & 7;
        const int cls = blockIdx.x >> 3;
        const int rbase = 8 * rank - 1;      // local row 0 = cell row rbase

        uint4* brec = (uint4*)sm;                                     // [1024]
        int* scs = (int*)(brec + BINCAP);                             // [1025]
        int* ccu = scs + 1025;                                        // [1024]
        unsigned short* hidx  = (unsigned short*)(ccu + 1024);        // [1024]
        unsigned short* wl    = hidx + BINCAP;                        // [1024]
        unsigned short* rlist = wl + BINCAP;                          // [1024]
        unsigned short* nbr   = rlist + BINCAP;                       // [1024*6]
        unsigned char* lstat  = (unsigned char*)(nbr + BINCAP * NBR_CAP); // [1024]
        unsigned char* nbrcnt = lstat + BINCAP;                       // [1024]
        int* warpsum = (int*)(nbrcnt + BINCAP);                       // [32]
        volatile unsigned char* vls = (volatile unsigned char*)lstat;
        volatile int* vg = (volatile int*)g_stat[cls];
        __shared__ int s_wl, s_nr;

        const int nbin = min(g_bincnt[cls][rank], BINCAP);

        scs[tid] = 0;
        if (tid == 0) { scs[1024] = 0; s_wl = 0; s_nr = 0; }
        __syncthreads();

        // pass 1: histogram over local cells
        for (int p = tid; p < nbin; p += NTHREADS) {
            uint4 R = g_binrec[cls][rank][p];
            int cx = min(63, max(0, (int)(__uint_as_float(R.z) * 0.125f)));
            int cy = min(63, max(0, (int)(__uint_as_float(R.w) * 0.125f)));
            atomicAdd(&scs[(cy - rbase) * 64 + cx], 1);
        }
        __syncthreads();
        {
            int v = scs[tid];
            int iv = warp_incl_scan(v);
            if (lane == 31) warpsum[wid] = iv;
            __syncthreads();
            if (wid == 0) warpsum[lane] = warp_incl_scan(warpsum[lane]);
            __syncthreads();
            int ex = iv - v + (wid ? warpsum[wid - 1] : 0);
            scs[tid] = ex; ccu[tid] = ex;
            if (tid == NTHREADS - 1) scs[1024] = ex + v;
        }
        __syncthreads();
        // pass 2: scatter into cell order
        for (int p = tid; p < nbin; p += NTHREADS) {
            uint4 R = g_binrec[cls][rank][p];
            int cx = min(63, max(0, (int)(__uint_as_float(R.z) * 0.125f)));
            int cy = min(63, max(0, (int)(__uint_as_float(R.w) * 0.125f)));
            int pos = atomicAdd(&ccu[(cy - rbase) * 64 + cx], 1);
            brec[pos] = R;
            hidx[pos] = g_binidx[cls][rank][p];
            lstat[pos] = R.y ? (unsigned char)0 : (unsigned char)2;
        }
        __syncthreads();

        const int pstart = scs[64];      // owned rows lr 1..8 => cells [64,576)
        const int pend   = scs[576];

        #define PUBLISH(p, idx, cy, v) do {                                   \
            vls[p] = (unsigned char)(v);                                      \
            int m_ = (cy) & 7;                                                \
            if ((m_ == 0 && rank > 0) || (m_ == 7 && rank < 7))               \
                vg[idx] = (int)(v);                                           \
        } while (0)

        // ---- edge build ----
        for (int p = pstart + tid; p < pend; p += NTHREADS) {
            uint4 R = brec[p];
            if (R.y == 0) continue;
            unsigned long long kj = ((unsigned long long)R.y << 32) | R.x;
            float xj = __uint_as_float(R.z), yj = __uint_as_float(R.w);
            int cx = min(63, max(0, (int)(xj * 0.125f)));
            int cy = min(63, max(0, (int)(yj * 0.125f)));
            int lr = cy - rbase;
            int x0 = max(cx - 1, 0), x1 = min(cx + 1, 63);
            unsigned short tmp[NBR_CAP];
            int cnt = 0;
            for (int rr = lr - 1; rr <= lr + 1; rr++) {
                int qs = scs[rr * 64 + x0];
                int qe = scs[rr * 64 + x1 + 1];
                for (int q = qs; q < qe; q++) {
                    uint4 C = brec[q];
                    unsigned long long ki = ((unsigned long long)C.y << 32) | C.x;
                    if (ki <= kj) continue;
                    float dx = __uint_as_float(C.z) - xj;
                    float dy = __uint_as_float(C.w) - yj;
                    if (dx * dx + dy * dy < D2_THRESH) {
                        if (cnt < NBR_CAP) {
                            bool rem = (q < pstart) || (q >= pend);
                            tmp[cnt] = rem ? (unsigned short)(0x8000u | hidx[q])
                                           : (unsigned short)q;
                        }
                        cnt++;
                    }
                }
            }
            int i = hidx[p];
            if (cnt == 0) {
                PUBLISH(p, i, cy, 1u);
                rlist[atomicAdd(&s_nr, 1)] = (unsigned short)p;
            } else {
                int w = atomicAdd(&s_wl, 1);
                wl[w] = (unsigned short)p;
                nbrcnt[w] = (cnt > NBR_CAP) ? (unsigned char)OVF : (unsigned char)cnt;
                #pragma unroll
                for (int k = 0; k < NBR_CAP; k++)
                    if (k < cnt) nbr[w * NBR_CAP + k] = tmp[k];
            }
        }
        __syncthreads();
        const int nwl = s_wl;

        // ---- dataflow resolve ----
        for (int w = tid; w < nwl; w += NTHREADS) {
            int p = wl[w];
            int i = hidx[p];
            uint4 R = brec[p];
            unsigned long long kj = ((unsigned long long)R.y << 32) | R.x;
            float xj = __uint_as_float(R.z), yj = __uint_as_float(R.w);
            int cy = min(63, max(0, (int)(yj * 0.125f)));
            int c = nbrcnt[w];
            unsigned int res = 0;
            if (c != OVF) {
                while (res == 0) {
                    bool sup = false, pend2 = false;
                    #pragma unroll 1
                    for (int k = 0; k < c; k++) {
                        unsigned short nb = nbr[w * NBR_CAP + k];
                        int st = (nb & 0x8000) ? vg[nb & 0x7FFF] : (int)vls[nb];
                        if (st == 1) { sup = true; break; }
                        if (st == 0) pend2 = true;
                    }
                    if (sup) res = 2;
                    else if (!pend2) res = 1;
                }
            } else {
                int cx = min(63, max(0, (int)(xj * 0.125f)));
                int lr = cy - rbase;
                int x0 = max(cx - 1, 0), x1 = min(cx + 1, 63);
                while (res == 0) {
                    bool sup = false, pend2 = false;
                    for (int rr = lr - 1; rr <= lr + 1 && !sup; rr++) {
                        int qs = scs[rr * 64 + x0];
                        int qe = scs[rr * 64 + x1 + 1];
                        for (int q = qs; q < qe; q++) {
                            uint4 C = brec[q];
                            unsigned long long ki = ((unsigned long long)C.y << 32) | C.x;
                            if (ki <= kj) continue;
                            float dx = __uint_as_float(C.z) - xj;
                            float dy = __uint_as_float(C.w) - yj;
                            if (dx * dx + dy * dy < D2_THRESH) {
                                bool rem2 = (q < pstart) || (q >= pend);
                                int st = rem2 ? vg[hidx[q]] : (int)vls[q];
                                if (st == 1) { sup = true; break; }
                                if (st == 0) pend2 = true;
                            }
                        }
                    }
                    if (sup) res = 2;
                    else if (!pend2) res = 1;
                }
            }
            PUBLISH(p, i, cy, res);
            if (res == 1) rlist[atomicAdd(&s_nr, 1)] = (unsigned short)p;
        }
        __syncthreads();

        // ---- emit retained after rank table ready ----
        const int nret = s_nr;
        if (tid == 0) {
            volatile int* vf = (volatile int*)&g_rankdone[cls];
            while (*vf == 0) { }
        }
        __syncthreads();
        for (int t = tid; t < nret; t += NTHREADS) {
            int p = rlist[t];
            int idx = hidx[p];
            unsigned int keyhi = brec[p].y;
            out[5 * (int)g_rank[cls][idx] + 3 + cls] = __uint_as_float(keyhi);
        }
        if (tid == 0) g_bincnt[cls][rank] = 0;   // reset for next replay
    }

    // ---- replay-safe reset of barrier/flags (last departing CTA) ----
    __syncthreads();
    if (tid == 0) {
        __threadfence();
        int d = atomicAdd(&g_depart, 1);
        if (d == NCTAS - 1) {
            g_arrive = 0;
            g_depart = 0;
            g_rankdone[0] = 0;
            g_rankdone[1] = 0;
            __threadfence();
        }
    }
}

extern "C" void kernel_launch(void* const* d_in, const int* in_sizes, int n_in,
                              void* d_out, int out_size) {
    const float* logits = (const float*)d_in[0];   // [1,4096,3]
    const float* boxes  = (const float*)d_in[1];   // [1,4096,2]
    // d_in[2] = pred_gids (unused by reference)
    const float* ts     = (const float*)d_in[3];   // [1,2] = (w,h)
    float* out = (float*)d_out;                    // [1,4096,5]

    cudaFuncSetAttribute(nms_fused_kernel,
                         cudaFuncAttributeMaxDynamicSharedMemorySize, SMEM_BYTES);
    nms_fused_kernel<<<NCTAS, NTHREADS, SMEM_BYTES>>>(logits, boxes, ts, out);
}

// round 17
// speedup vs baseline: 1.0272x; 1.0272x over previous
#include <cuda_runtime.h>
#include <cstdint>

#define N_Q 4096
#define NTHREADS 1024
#define NSTRIPE 16
#define EVAL_PT_SCORE 0.05f
#define D2_THRESH 25.0f   // 5.0^2
#define NBR_CAP 6
#define OVF 255
#define BINCAP 768        // 6-row slice, expected ~384
#define WCAP 512
#define NBUCK 1024

#define SMEM_BYTES 41864

// -------- device scratch --------
__device__ uint4 g_binrec[2][NSTRIPE][BINCAP];  // (keylo,keyhi,x,y) per stripe bin
__device__ unsigned short g_binidx[2][NSTRIPE][BINCAP];
__device__ int g_bincnt[2][NSTRIPE];
__device__ unsigned long long g_key[2][N_Q];
__device__ int g_stat[2][N_Q];                  // 0 pending / 1 retained / 2 suppressed
__device__ unsigned short g_rank[2][N_Q];
__device__ int g_rankdone[2];

__device__ __forceinline__ int warp_incl_scan(int v) {
    int lane = threadIdx.x & 31;
    #pragma unroll
    for (int o = 1; o < 32; o <<= 1) {
        int n = __shfl_up_sync(0xffffffffu, v, o);
        if (lane >= o) v += n;
    }
    return v;
}

__device__ __forceinline__ unsigned long long mk_key(float s, int i) {
    bool valid = (s >= EVAL_PT_SCORE);
    unsigned int fb = __float_as_uint(s);
    return valid
        ? ((((unsigned long long)fb) << 32) | (unsigned int)(N_Q - 1 - i))
        : (unsigned long long)(unsigned int)(N_Q - 1 - i);
}

// ---------------- K1: prep (8 CTAs, 1 pt/thread) ----------------
__global__ void __launch_bounds__(NTHREADS)
prep_kernel(const float* __restrict__ logits,
            const float* __restrict__ boxes,
            const float* __restrict__ ts,
            float* __restrict__ out) {
    int t = blockIdx.x * NTHREADS + threadIdx.x;   // 0..8191
    if (t == 0) { g_rankdone[0] = 0; g_rankdone[1] = 0; }
    int cls = t >> 12;
    int j = t & (N_Q - 1);
    float l0 = logits[3 * j + 0];
    float l1 = logits[3 * j + 1];
    float l2 = logits[3 * j + 2];
    float m = fmaxf(l0, fmaxf(l1, l2));
    float e0 = __expf(l0 - m), e1 = __expf(l1 - m), e2 = __expf(l2 - m);
    float inv = __fdividef(1.0f, e0 + e1 + e2);
    float p0 = e0 * inv, p1 = e1 * inv, p2 = e2 * inv;
    float x = boxes[2 * j + 0] * ts[0];
    float y = boxes[2 * j + 1] * ts[1];
    float s = cls ? p1 : p0;
    unsigned long long key = mk_key(s, j);
    g_key[cls][j] = key;
    g_stat[cls][j] = (s >= EVAL_PT_SCORE) ? 0 : 2;

    int cy = min(63, max(0, (int)(y * 0.125f)));
    uint4 rec = make_uint4((unsigned int)key, (unsigned int)(key >> 32),
                           __float_as_uint(x), __float_as_uint(y));
    int b0 = cy >> 2, mrow = cy & 3;
    {
        int pos = atomicAdd(&g_bincnt[cls][b0], 1);
        if (pos < BINCAP) { g_binrec[cls][b0][pos] = rec; g_binidx[cls][b0][pos] = (unsigned short)j; }
    }
    if (mrow == 0 && b0 > 0) {
        int pos = atomicAdd(&g_bincnt[cls][b0 - 1], 1);
        if (pos < BINCAP) { g_binrec[cls][b0 - 1][pos] = rec; g_binidx[cls][b0 - 1][pos] = (unsigned short)j; }
    }
    if (mrow == 3 && b0 < NSTRIPE - 1) {
        int pos = atomicAdd(&g_bincnt[cls][b0 + 1], 1);
        if (pos < BINCAP) { g_binrec[cls][b0 + 1][pos] = rec; g_binidx[cls][b0 + 1][pos] = (unsigned short)j; }
    }

    if (cls == 0) {
        out[5 * j + 0] = 1.0f - p2;
        out[5 * j + 1] = x;
        out[5 * j + 2] = y;
        out[5 * j + 3] = 0.0f;
    } else {
        out[5 * j + 4] = 0.0f;
    }
}

// ---------------- K2: 32 stripe resolvers + 2 rank builders ----------------
__global__ void __launch_bounds__(NTHREADS, 1)
resolve_kernel(float* __restrict__ out) {
    const int tid = threadIdx.x;
    const int lane = tid & 31;
    const int wid = tid >> 5;
    extern __shared__ unsigned char sm[];

    if (blockIdx.x >= 32) {
        // ======== rank builder for class cls ========
        const int cls = blockIdx.x - 32;
        unsigned long long* bkey = (unsigned long long*)sm;        // [N_Q]
        int* cs  = (int*)(bkey + N_Q);                             // [NBUCK+1]
        int* ccu = cs + (NBUCK + 1);                               // [NBUCK]
        int* warpsum = ccu + NBUCK;                                // [32]

        cs[tid] = 0;
        if (tid == 0) cs[NBUCK] = 0;
        __syncthreads();

        unsigned long long k4[4];
        int b4[4];
        #pragma unroll
        for (int k = 0; k < 4; k++) {
            int j = k * NTHREADS + tid;
            unsigned long long key = g_key[cls][j];
            k4[k] = key;
            if (key >> 32) {
                float s = __uint_as_float((unsigned int)(key >> 32));
                b4[k] = min(NBUCK - 1, (int)(s * (float)NBUCK));
                atomicAdd(&cs[b4[k]], 1);
            } else b4[k] = 0;
        }
        __syncthreads();
        {
            int v = cs[tid];
            int iv = warp_incl_scan(v);
            if (lane == 31) warpsum[wid] = iv;
            __syncthreads();
            if (wid == 0) warpsum[lane] = warp_incl_scan(warpsum[lane]);
            __syncthreads();
            int ex = iv - v + (wid ? warpsum[wid - 1] : 0);
            cs[tid] = ex; ccu[tid] = ex;
            if (tid == NTHREADS - 1) cs[NBUCK] = ex + v;
        }
        __syncthreads();
        const int nv = cs[NBUCK];
        #pragma unroll
        for (int k = 0; k < 4; k++) {
            if (k4[k] >> 32) {
                int bp = atomicAdd(&ccu[b4[k]], 1);
                bkey[bp] = k4[k];
            }
        }
        __syncthreads();
        #pragma unroll
        for (int k = 0; k < 4; k++) {
            if (!(k4[k] >> 32)) continue;
            int b = b4[k];
            int r = nv - cs[b + 1];
            int e = cs[b + 1];
            for (int q = cs[b]; q < e; q++)
                if (bkey[q] > k4[k]) r++;
            g_rank[cls][k * NTHREADS + tid] = (unsigned short)r;
        }
        __syncthreads();
        __threadfence();
        if (tid == 0) g_rankdone[cls] = 1;
        return;
    }

    // ======== stripe resolver (4 owned cell-rows + 1 halo row each side) ========
    const int rs = blockIdx.x & (NSTRIPE - 1);
    const int cls = blockIdx.x >> 4;
    const int rbase = 4 * rs - 1;            // local row 0 = cell row rbase

    uint4* srec = (uint4*)sm;                                     // [BINCAP] staged
    uint4* brec = srec + BINCAP;                                  // [BINCAP] cell-ordered
    int* scs = (int*)(brec + BINCAP);                             // [385]
    int* ccu = scs + 385;                                         // [384]
    int* warpsum = ccu + 384;                                     // [32]
    unsigned short* sidx  = (unsigned short*)(warpsum + 32);      // [BINCAP]
    unsigned short* scell = sidx + BINCAP;                        // [BINCAP]
    unsigned short* hidx  = scell + BINCAP;                       // [BINCAP]
    unsigned short* wl    = hidx + BINCAP;                        // [WCAP]
    unsigned short* rlist = wl + WCAP;                            // [WCAP]
    unsigned short* nbr   = rlist + WCAP;                         // [WCAP*6]
    unsigned char* lstat  = (unsigned char*)(nbr + WCAP * NBR_CAP); // [BINCAP]
    unsigned char* nbrcnt = lstat + BINCAP;                       // [WCAP]
    volatile unsigned char* vls = (volatile unsigned char*)lstat;
    volatile int* vg = (volatile int*)g_stat[cls];
    __shared__ int s_wl, s_nr;

    const int nbin = min(g_bincnt[cls][rs], BINCAP);

    if (tid < 385) scs[tid] = 0;
    if (tid == 0) { s_wl = 0; s_nr = 0; }
    __syncthreads();

    // stage bin into smem once + histogram
    for (int p = tid; p < nbin; p += NTHREADS) {
        uint4 R = g_binrec[cls][rs][p];
        srec[p] = R;
        sidx[p] = g_binidx[cls][rs][p];
        int cx = min(63, max(0, (int)(__uint_as_float(R.z) * 0.125f)));
        int cy = min(63, max(0, (int)(__uint_as_float(R.w) * 0.125f)));
        int lc = (cy - rbase) * 64 + cx;     // lr in [0,5]
        scell[p] = (unsigned short)lc;
        atomicAdd(&scs[lc], 1);
    }
    __syncthreads();
    // scan 384 cells
    {
        int v = (tid < 384) ? scs[tid] : 0;
        int iv = warp_incl_scan(v);
        if (lane == 31) warpsum[wid] = iv;
        __syncthreads();
        if (wid == 0) warpsum[lane] = warp_incl_scan(warpsum[lane]);
        __syncthreads();
        int ex = iv - v + (wid ? warpsum[wid - 1] : 0);
        if (tid < 384) { scs[tid] = ex; ccu[tid] = ex; }
        if (tid == 384 - 1) scs[384] = ex + v;   // total (tid 383 holds last)
    }
    __syncthreads();
    // scatter smem -> smem into cell order
    for (int p = tid; p < nbin; p += NTHREADS) {
        uint4 R = srec[p];
        int pos = atomicAdd(&ccu[scell[p]], 1);
        brec[pos] = R;
        hidx[pos] = sidx[p];
        lstat[pos] = R.y ? (unsigned char)0 : (unsigned char)2;
    }
    __syncthreads();

    const int pstart = scs[64];          // owned rows lr 1..4 => cells [64,320)
    const int pend   = scs[320];

    #define PUBLISH(p, idx, cy, v) do {                                       \
        vls[p] = (unsigned char)(v);                                          \
        int m_ = (cy) & 3;                                                    \
        if ((m_ == 0 && rs > 0) || (m_ == 3 && rs < NSTRIPE - 1))             \
            vg[idx] = (int)(v);                                               \
    } while (0)

    // ---- edge build for owned records ----
    for (int p = pstart + tid; p < pend; p += NTHREADS) {
        uint4 R = brec[p];
        if (R.y == 0) continue;
        unsigned long long kj = ((unsigned long long)R.y << 32) | R.x;
        float xj = __uint_as_float(R.z), yj = __uint_as_float(R.w);
        int cx = min(63, max(0, (int)(xj * 0.125f)));
        int cy = min(63, max(0, (int)(yj * 0.125f)));
        int lr = cy - rbase;                 // 1..4
        int x0 = max(cx - 1, 0), x1 = min(cx + 1, 63);
        unsigned short tmp[NBR_CAP];
        int cnt = 0;
        for (int rr = lr - 1; rr <= lr + 1; rr++) {
            int qs = scs[rr * 64 + x0];
            int qe = scs[rr * 64 + x1 + 1];
            for (int q = qs; q < qe; q++) {
                uint4 C = brec[q];
                unsigned long long ki = ((unsigned long long)C.y << 32) | C.x;
                if (ki <= kj) continue;
                float dx = __uint_as_float(C.z) - xj;
                float dy = __uint_as_float(C.w) - yj;
                if (dx * dx + dy * dy < D2_THRESH) {
                    if (cnt < NBR_CAP) {
                        bool rem = (q < pstart) || (q >= pend);
                        tmp[cnt] = rem ? (unsigned short)(0x8000u | hidx[q])
                                       : (unsigned short)q;
                    }
                    cnt++;
                }
            }
        }
        int i = hidx[p];
        if (cnt == 0) {
            PUBLISH(p, i, cy, 1u);
            rlist[atomicAdd(&s_nr, 1)] = (unsigned short)p;
        } else {
            int w = atomicAdd(&s_wl, 1);
            wl[w] = (unsigned short)p;
            nbrcnt[w] = (cnt > NBR_CAP) ? (unsigned char)OVF : (unsigned char)cnt;
            #pragma unroll
            for (int k = 0; k < NBR_CAP; k++)
                if (k < cnt) nbr[w * NBR_CAP + k] = tmp[k];
        }
    }
    __syncthreads();
    const int nwl = s_wl;

    // ---- dataflow resolve: local smem / remote L2 ----
    for (int w = tid; w < nwl; w += NTHREADS) {
        int p = wl[w];
        int i = hidx[p];
        uint4 R = brec[p];
        unsigned long long kj = ((unsigned long long)R.y << 32) | R.x;
        float xj = __uint_as_float(R.z), yj = __uint_as_float(R.w);
        int cy = min(63, max(0, (int)(yj * 0.125f)));
        int c = nbrcnt[w];
        unsigned int res = 0;
        if (c != OVF) {
            while (res == 0) {
                bool sup = false, pend2 = false;
                #pragma unroll 1
                for (int k = 0; k < c; k++) {
                    unsigned short nb = nbr[w * NBR_CAP + k];
                    int st = (nb & 0x8000) ? vg[nb & 0x7FFF] : (int)vls[nb];
                    if (st == 1) { sup = true; break; }
                    if (st == 0) pend2 = true;
                }
                if (sup) res = 2;
                else if (!pend2) res = 1;
            }
        } else {
            int cx = min(63, max(0, (int)(xj * 0.125f)));
            int lr = cy - rbase;
            int x0 = max(cx - 1, 0), x1 = min(cx + 1, 63);
            while (res == 0) {
                bool sup = false, pend2 = false;
                for (int rr = lr - 1; rr <= lr + 1 && !sup; rr++) {
                    int qs = scs[rr * 64 + x0];
                    int qe = scs[rr * 64 + x1 + 1];
                    for (int q = qs; q < qe; q++) {
                        uint4 C = brec[q];
                        unsigned long long ki = ((unsigned long long)C.y << 32) | C.x;
                        if (ki <= kj) continue;
                        float dx = __uint_as_float(C.z) - xj;
                        float dy = __uint_as_float(C.w) - yj;
                        if (dx * dx + dy * dy < D2_THRESH) {
                            bool rem2 = (q < pstart) || (q >= pend);
                            int st = rem2 ? vg[hidx[q]] : (int)vls[q];
                            if (st == 1) { sup = true; break; }
                            if (st == 0) pend2 = true;
                        }
                    }
                }
                if (sup) res = 2;
                else if (!pend2) res = 1;
            }
        }
        PUBLISH(p, i, cy, res);
        if (res == 1) rlist[atomicAdd(&s_nr, 1)] = (unsigned short)p;
    }
    __syncthreads();

    // ---- emit retained after rank table ready ----
    const int nret = s_nr;
    if (tid == 0) {
        volatile int* vf = (volatile int*)&g_rankdone[cls];
        while (*vf == 0) { }
    }
    __syncthreads();
    for (int t = tid; t < nret; t += NTHREADS) {
        int p = rlist[t];
        int idx = hidx[p];
        unsigned int keyhi = brec[p].y;
        out[5 * (int)g_rank[cls][idx] + 3 + cls] = __uint_as_float(keyhi);
    }
    if (tid == 0) g_bincnt[cls][rs] = 0;     // reset cursor for next replay
}

extern "C" void kernel_launch(void* const* d_in, const int* in_sizes, int n_in,
                              void* d_out, int out_size) {
    const float* logits = (const float*)d_in[0];   // [1,4096,3]
    const float* boxes  = (const float*)d_in[1];   // [1,4096,2]
    // d_in[2] = pred_gids (unused by reference)
    const float* ts     = (const float*)d_in[3];   // [1,2] = (w,h)
    float* out = (float*)d_out;                    // [1,4096,5]

    prep_kernel<<<2 * N_Q / NTHREADS, NTHREADS>>>(logits, boxes, ts, out);

    cudaFuncSetAttribute(resolve_kernel,
                         cudaFuncAttributeMaxDynamicSharedMemorySize, SMEM_BYTES);
    resolve_kernel<<<34, NTHREADS, SMEM_BYTES>>>(out);
}